// round 3
// baseline (speedup 1.0000x reference)
#include <cuda_runtime.h>
#include <math.h>

#define BATCH 64
#define SEQ   512
#define EMBD  256
#define HIDD  512
#define GATES 2048      // 4*HIDD
#define WROW  768       // EMBD + HIDD
#define NCLS  50257
#define RCTAS 128       // persistent recurrence CTAs (<=148 -> co-resident)

// ---------------- device-global scratch (no runtime allocation allowed) ----
__device__ float g_xproj[(size_t)SEQ * GATES * BATCH];   // [t][g][b]
__device__ float g_h[2][BATCH * HIDD];                   // double-buffered h [b][k]
__device__ float g_C[HIDD * BATCH];                      // cell state [j][b] (idx=j*64+b)
__device__ float g_part[4][GATES * BATCH];               // K-split partials [kc][g][b]
__device__ unsigned g_bar_count;
__device__ volatile unsigned g_bar_sense;

// ---------------- init: zero h0, C, barrier state ----------------
__global__ void k_init() {
    int i = blockIdx.x * 256 + threadIdx.x;
    if (i < BATCH * HIDD) {
        g_h[0][i] = 0.0f;
        g_C[i]    = 0.0f;
    }
    if (i == 0) { g_bar_count = 0; g_bar_sense = 0; }
}

// ---------------- grid barrier (sense = monotone phase counter) ------------
__device__ __forceinline__ void grid_bar(unsigned phase) {
    __syncthreads();
    if (threadIdx.x == 0) {
        __threadfence();
        unsigned old = atomicAdd(&g_bar_count, 1u);
        if (old == RCTAS - 1) {
            g_bar_count = 0;
            __threadfence();
            g_bar_sense = phase;
        } else {
            while (g_bar_sense < phase) { }
            __threadfence();
        }
    }
    __syncthreads();
}

// ---------------- Kernel 1: Xproj[t][g][b] = emb[x[b,t]] . Wx[g] + bias[g] --
__global__ __launch_bounds__(256) void k_xproj(const int* __restrict__ x,
                                               const float* __restrict__ emb,
                                               const float* __restrict__ W,
                                               const float* __restrict__ Wb) {
    const int t  = blockIdx.y;
    const int g0 = blockIdx.x * 64;

    __shared__ float a_s[64][20];   // [b][k]
    __shared__ float w_s[64][20];   // [g][k]
    __shared__ int   tok[64];

    const int tid = threadIdx.x;
    if (tid < 64) tok[tid] = x[tid * SEQ + t];
    __syncthreads();

    const int tx = tid & 15;   // -> b group
    const int ty = tid >> 4;   // -> g group

    float acc[4][4];            // [gi][bi]
#pragma unroll
    for (int i = 0; i < 4; i++)
#pragma unroll
        for (int j = 0; j < 4; j++) acc[i][j] = 0.0f;

    const int lr = tid >> 2;          // row 0..63
    const int lk = (tid & 3) * 4;     // 0,4,8,12

    for (int k0 = 0; k0 < EMBD; k0 += 16) {
        float4 av = *(const float4*)&emb[(size_t)tok[lr] * EMBD + k0 + lk];
        float4 wv = *(const float4*)&W[(size_t)(g0 + lr) * WROW + k0 + lk];
        *(float4*)&a_s[lr][lk] = av;
        *(float4*)&w_s[lr][lk] = wv;
        __syncthreads();

#pragma unroll
        for (int k = 0; k < 16; k += 4) {
            float4 af[4], wf[4];
#pragma unroll
            for (int i = 0; i < 4; i++) af[i] = *(const float4*)&a_s[tx * 4 + i][k];
#pragma unroll
            for (int i = 0; i < 4; i++) wf[i] = *(const float4*)&w_s[ty * 4 + i][k];
#pragma unroll
            for (int gi = 0; gi < 4; gi++)
#pragma unroll
                for (int bi = 0; bi < 4; bi++) {
                    acc[gi][bi] += af[bi].x * wf[gi].x;
                    acc[gi][bi] += af[bi].y * wf[gi].y;
                    acc[gi][bi] += af[bi].z * wf[gi].z;
                    acc[gi][bi] += af[bi].w * wf[gi].w;
                }
        }
        __syncthreads();
    }

#pragma unroll
    for (int gi = 0; gi < 4; gi++) {
        int g = g0 + ty * 4 + gi;
        float bias = Wb[g];
        float4 v;
        v.x = acc[gi][0] + bias;
        v.y = acc[gi][1] + bias;
        v.z = acc[gi][2] + bias;
        v.w = acc[gi][3] + bias;
        *(float4*)&g_xproj[((size_t)t * GATES + g) * BATCH + tx * 4] = v;
    }
}

// ---------------- Kernel 2: persistent recurrence ---------------------------
// 128 CTAs: gt = bx&31 (64-gate tile), kc = bx>>5 (128-k chunk).
// Per step: GEMM partials -> barrier -> elementwise cell -> barrier.
// Wh tile (64g x 128k, 32KB) preloaded into smem ONCE.
__global__ __launch_bounds__(256) void k_recur(const float* __restrict__ W) {
    const int bx = blockIdx.x;
    const int gt = bx & 31;
    const int kc = bx >> 5;
    const int g0 = gt * 64;
    const int kbase = kc * 128;

    __shared__ float w_s[64][132];   // [g][k] full 128-k tile, resident
    __shared__ float h_s[64][36];    // [b][k] 32-k stage

    const int tid = threadIdx.x;
    const int tx = tid & 15;         // -> b group
    const int ty = tid >> 4;         // -> g group

    // Preload Wh tile once: 64 rows x 128 k = 2048 float4, 8 per thread
#pragma unroll
    for (int i = 0; i < 8; i++) {
        int lin = tid + i * 256;     // float4 slot 0..2047
        int r   = lin >> 5;          // row 0..63
        int kq  = (lin & 31) * 4;    // 0..124
        *(float4*)&w_s[r][kq] =
            *(const float4*)&W[(size_t)(g0 + r) * WROW + EMBD + kbase + kq];
    }
    __syncthreads();

    unsigned phase = 0;

    for (int t = 0; t < SEQ; t++) {
        const float* __restrict__ h = g_h[t & 1];

        float acc[4][4];
#pragma unroll
        for (int i = 0; i < 4; i++)
#pragma unroll
            for (int j = 0; j < 4; j++) acc[i][j] = 0.0f;

        for (int kk = 0; kk < 128; kk += 32) {
            // stage 64b x 32k of h: 512 float4, 2 per thread
#pragma unroll
            for (int i = 0; i < 2; i++) {
                int lin = tid + i * 256;   // 0..511
                int r   = lin >> 3;        // row 0..63
                int kq  = (lin & 7) * 4;   // 0..28
                *(float4*)&h_s[r][kq] = *(const float4*)&h[r * HIDD + kbase + kk + kq];
            }
            __syncthreads();

#pragma unroll
            for (int k = 0; k < 32; k += 4) {
                float4 hf[4], wf[4];
#pragma unroll
                for (int i = 0; i < 4; i++) hf[i] = *(const float4*)&h_s[tx * 4 + i][k];
#pragma unroll
                for (int i = 0; i < 4; i++) wf[i] = *(const float4*)&w_s[ty * 4 + i][kk + k];
#pragma unroll
                for (int gi = 0; gi < 4; gi++)
#pragma unroll
                    for (int bi = 0; bi < 4; bi++) {
                        acc[gi][bi] += hf[bi].x * wf[gi].x;
                        acc[gi][bi] += hf[bi].y * wf[gi].y;
                        acc[gi][bi] += hf[bi].z * wf[gi].z;
                        acc[gi][bi] += hf[bi].w * wf[gi].w;
                    }
            }
            __syncthreads();
        }

#pragma unroll
        for (int gi = 0; gi < 4; gi++) {
            int g = g0 + ty * 4 + gi;
            float4 v;
            v.x = acc[gi][0]; v.y = acc[gi][1]; v.z = acc[gi][2]; v.w = acc[gi][3];
            *(float4*)&g_part[kc][g * BATCH + tx * 4] = v;
        }

        grid_bar(++phase);   // partials visible to all

        // ---- elementwise cell: this CTA owns idx = bx*256 + tid ----
        {
            const int idx = bx * 256 + tid;      // 0..32767
            const int j = idx >> 6;
            const int b = idx & 63;

            float v[4];
#pragma unroll
            for (int q = 0; q < 4; q++) {
                int g = q * HIDD + j;
                float s = g_xproj[((size_t)t * GATES + g) * BATCH + b];
#pragma unroll
                for (int c = 0; c < 4; c++) s += g_part[c][g * BATCH + b];
                v[q] = s;
            }

            float f  = 1.0f / (1.0f + expf(-v[0]));
            float ig = 1.0f / (1.0f + expf(-v[1]));
            float o  = 1.0f / (1.0f + expf(-v[2]));
            float ct = tanhf(v[3]);

            float C = f * g_C[idx] + ig * ct;
            g_C[idx] = C;
            g_h[(t + 1) & 1][b * HIDD + j] = o * tanhf(C);
        }

        grid_bar(++phase);   // new h visible before next step's GEMM
    }
}

// ---------------- Kernel 4: FC head  out[b][n] = h[b].fc[n] + bias ----------
__global__ __launch_bounds__(256) void k_fc(const float* __restrict__ fcw,
                                            const float* __restrict__ fcb,
                                            float* __restrict__ out) {
    const int n0 = blockIdx.x * 64;
    const float* __restrict__ h = g_h[0];   // t=511 wrote buffer (512&1)=0

    __shared__ float h_s[64][68];   // [b][k]
    __shared__ float w_s[64][68];   // [n][k]

    const int tid = threadIdx.x;
    const int tx = tid & 15;        // -> n group
    const int ty = tid >> 4;        // -> b group

    float acc[4][4];                // [bi][ni]
#pragma unroll
    for (int i = 0; i < 4; i++)
#pragma unroll
        for (int j = 0; j < 4; j++) acc[i][j] = 0.0f;

    for (int k0 = 0; k0 < HIDD; k0 += 64) {
#pragma unroll
        for (int i = 0; i < 4; i++) {
            int lin = tid + i * 256;
            int r   = lin >> 4;
            int kq  = (lin & 15) * 4;
            *(float4*)&h_s[r][kq] = *(const float4*)&h[r * HIDD + k0 + kq];
            int n = n0 + r;
            float4 wv = make_float4(0.f, 0.f, 0.f, 0.f);
            if (n < NCLS) wv = *(const float4*)&fcw[(size_t)n * HIDD + k0 + kq];
            *(float4*)&w_s[r][kq] = wv;
        }
        __syncthreads();

#pragma unroll
        for (int k = 0; k < 64; k += 4) {
            float4 hf[4], wf[4];
#pragma unroll
            for (int i = 0; i < 4; i++) hf[i] = *(const float4*)&h_s[ty * 4 + i][k];
#pragma unroll
            for (int i = 0; i < 4; i++) wf[i] = *(const float4*)&w_s[tx * 4 + i][k];
#pragma unroll
            for (int bi = 0; bi < 4; bi++)
#pragma unroll
                for (int ni = 0; ni < 4; ni++) {
                    acc[bi][ni] += hf[bi].x * wf[ni].x;
                    acc[bi][ni] += hf[bi].y * wf[ni].y;
                    acc[bi][ni] += hf[bi].z * wf[ni].z;
                    acc[bi][ni] += hf[bi].w * wf[ni].w;
                }
        }
        __syncthreads();
    }

#pragma unroll
    for (int bi = 0; bi < 4; bi++) {
        int b = ty * 4 + bi;
#pragma unroll
        for (int ni = 0; ni < 4; ni++) {
            int n = n0 + tx * 4 + ni;
            if (n < NCLS) out[(size_t)b * NCLS + n] = acc[bi][ni] + fcb[n];
        }
    }
}

// ---------------- launch ----------------
extern "C" void kernel_launch(void* const* d_in, const int* in_sizes, int n_in,
                              void* d_out, int out_size) {
    const int*   x   = (const int*)  d_in[0];
    const float* emb = (const float*)d_in[1];
    const float* W   = (const float*)d_in[2];
    const float* Wb  = (const float*)d_in[3];
    const float* fcw = (const float*)d_in[4];
    const float* fcb = (const float*)d_in[5];
    float* out = (float*)d_out;

    k_init<<<(BATCH * HIDD + 255) / 256, 256>>>();
    k_xproj<<<dim3(32, SEQ), 256>>>(x, emb, W, Wb);
    k_recur<<<RCTAS, 256>>>(W);
    k_fc<<<(NCLS + 63) / 64, 256>>>(fcw, fcb, out);
}